// round 2
// baseline (speedup 1.0000x reference)
#include <cuda_runtime.h>
#include <math.h>

#define S 2048
#define B 2
#define STILE 4

// Scratch for normalized q and k: [which(q=0,k=1)][b][n][blade] = 256 KB
__device__ float g_qk[2][B][S][8];

// ---------------------------------------------------------------------------
// Kernel 1: q AND k for row n in one block.
//   q[b,n,i] = sum_m Wq[n,m,g(i)] * x[b,m,i]   (same for k with Wk)
// Grid: S blocks, 256 threads. Streams 64 KB of W per block (MLP=8 DRAM loads).
// ---------------------------------------------------------------------------
__global__ __launch_bounds__(256) void qk_kernel(
    const float* __restrict__ x,    // (B, S, 8)
    const float* __restrict__ Wq,   // (S, S, 4)
    const float* __restrict__ Wk,   // (S, S, 4)
    const float* __restrict__ a)    // (3000, 4)
{
    const int n   = blockIdx.x;
    const int tid = threadIdx.x;

    const float4* WqR = reinterpret_cast<const float4*>(Wq + (size_t)n * S * 4);
    const float4* WkR = reinterpret_cast<const float4*>(Wk + (size_t)n * S * 4);
    const float4* X   = reinterpret_cast<const float4*>(x);

    float aq[16], ak[16];
#pragma unroll
    for (int i = 0; i < 16; i++) { aq[i] = 0.f; ak[i] = 0.f; }

#pragma unroll 4
    for (int m = tid; m < S; m += 256) {
        float4 wq  = WqR[m];
        float4 wk  = WkR[m];
        float4 x0a = X[m * 2 + 0];
        float4 x0b = X[m * 2 + 1];
        float4 x1a = X[(S + m) * 2 + 0];
        float4 x1b = X[(S + m) * 2 + 1];

        aq[0]  = fmaf(wq.x, x0a.x, aq[0]);
        aq[1]  = fmaf(wq.y, x0a.y, aq[1]);
        aq[2]  = fmaf(wq.y, x0a.z, aq[2]);
        aq[3]  = fmaf(wq.y, x0a.w, aq[3]);
        aq[4]  = fmaf(wq.z, x0b.x, aq[4]);
        aq[5]  = fmaf(wq.z, x0b.y, aq[5]);
        aq[6]  = fmaf(wq.z, x0b.z, aq[6]);
        aq[7]  = fmaf(wq.w, x0b.w, aq[7]);
        aq[8]  = fmaf(wq.x, x1a.x, aq[8]);
        aq[9]  = fmaf(wq.y, x1a.y, aq[9]);
        aq[10] = fmaf(wq.y, x1a.z, aq[10]);
        aq[11] = fmaf(wq.y, x1a.w, aq[11]);
        aq[12] = fmaf(wq.z, x1b.x, aq[12]);
        aq[13] = fmaf(wq.z, x1b.y, aq[13]);
        aq[14] = fmaf(wq.z, x1b.z, aq[14]);
        aq[15] = fmaf(wq.w, x1b.w, aq[15]);

        ak[0]  = fmaf(wk.x, x0a.x, ak[0]);
        ak[1]  = fmaf(wk.y, x0a.y, ak[1]);
        ak[2]  = fmaf(wk.y, x0a.z, ak[2]);
        ak[3]  = fmaf(wk.y, x0a.w, ak[3]);
        ak[4]  = fmaf(wk.z, x0b.x, ak[4]);
        ak[5]  = fmaf(wk.z, x0b.y, ak[5]);
        ak[6]  = fmaf(wk.z, x0b.z, ak[6]);
        ak[7]  = fmaf(wk.w, x0b.w, ak[7]);
        ak[8]  = fmaf(wk.x, x1a.x, ak[8]);
        ak[9]  = fmaf(wk.y, x1a.y, ak[9]);
        ak[10] = fmaf(wk.y, x1a.z, ak[10]);
        ak[11] = fmaf(wk.y, x1a.w, ak[11]);
        ak[12] = fmaf(wk.z, x1b.x, ak[12]);
        ak[13] = fmaf(wk.z, x1b.y, ak[13]);
        ak[14] = fmaf(wk.z, x1b.z, ak[14]);
        ak[15] = fmaf(wk.w, x1b.w, ak[15]);
    }

    // Warp reduction of 32 accumulators
#pragma unroll
    for (int i = 0; i < 16; i++) {
#pragma unroll
        for (int off = 16; off > 0; off >>= 1) {
            aq[i] += __shfl_down_sync(0xffffffffu, aq[i], off);
            ak[i] += __shfl_down_sync(0xffffffffu, ak[i], off);
        }
    }

    __shared__ float red[8][32];
    __shared__ float vals[32];          // [0..15]=q (b0,b1), [16..31]=k
    __shared__ float denom[2][B][4];
    const int warp = tid >> 5, lane = tid & 31;
    if (lane == 0) {
#pragma unroll
        for (int i = 0; i < 16; i++) {
            red[warp][i]      = aq[i];
            red[warp][16 + i] = ak[i];
        }
    }
    __syncthreads();

    if (tid < 32) {
        float s = 0.f;
#pragma unroll
        for (int w2 = 0; w2 < 8; w2++) s += red[w2][tid];
        vals[tid] = s;
    }
    __syncthreads();

    if (tid < 4) {
        const int which = tid >> 1, b = tid & 1;
        const float* v = &vals[which * 16 + b * 8];
        float nr[4];
        nr[0] = fabsf(v[0]);
        nr[1] = sqrtf(v[1] * v[1] + v[2] * v[2] + v[3] * v[3]);
        nr[2] = sqrtf(v[4] * v[4] + v[5] * v[5] + v[6] * v[6]);
        nr[3] = fabsf(v[7]);
#pragma unroll
        for (int g = 0; g < 4; g++) {
            float sa = 1.f / (1.f + expf(-a[n * 4 + g]));
            denom[which][b][g] = sa * (nr[g] - 1.f) + 1.f + 1e-6f;
        }
    }
    __syncthreads();

    if (tid < 32) {
        const int which = tid >> 4, r = tid & 15;
        const int b = r >> 3, i = r & 7;
        const int g = (i == 0) ? 0 : (i < 4) ? 1 : (i < 7) ? 2 : 3;
        g_qk[which][b][n][i] = vals[tid] / denom[which][b][g];
    }
}

// ---------------------------------------------------------------------------
// Kernel 2: out[b,s,t,:] = q[b,s,:] (geometric product) k[b,t,:]
// STILE=4 s-rows per block: K loaded once, reused 4x (L1 load traffic /4).
// Grid: (S/STILE, B), 256 threads; each thread covers 8 t's per s-row.
// ---------------------------------------------------------------------------
__global__ __launch_bounds__(256) void gp_kernel(float* __restrict__ out)
{
    const int s0  = blockIdx.x * STILE;
    const int b   = blockIdx.y;
    const int tid = threadIdx.x;

    float q[STILE][8];
#pragma unroll
    for (int si = 0; si < STILE; si++) {
        const float4 qa = *reinterpret_cast<const float4*>(&g_qk[0][b][s0 + si][0]);
        const float4 qb = *reinterpret_cast<const float4*>(&g_qk[0][b][s0 + si][4]);
        q[si][0] = qa.x; q[si][1] = qa.y; q[si][2] = qa.z; q[si][3] = qa.w;
        q[si][4] = qb.x; q[si][5] = qb.y; q[si][6] = qb.z; q[si][7] = qb.w;
    }

    const float4* K = reinterpret_cast<const float4*>(&g_qk[1][b][0][0]);
    float4* obase = reinterpret_cast<float4*>(out + (((size_t)b * S + s0) * S) * 8);

#pragma unroll
    for (int it = 0; it < 8; it++) {
        const int t = tid + it * 256;
        const float4 ka = K[t * 2 + 0];
        const float4 kb = K[t * 2 + 1];
        const float k0 = ka.x, k1 = ka.y, k2 = ka.z, k3 = ka.w;
        const float k4 = kb.x, k5 = kb.y, k6 = kb.z, k7 = kb.w;

#pragma unroll
        for (int si = 0; si < STILE; si++) {
            const float q0 = q[si][0], q1 = q[si][1], q2 = q[si][2], q3 = q[si][3];
            const float q4 = q[si][4], q5 = q[si][5], q6 = q[si][6], q7 = q[si][7];

            float4 o_lo, o_hi;
            o_lo.x = q0*k0 + q1*k1 + q2*k2 + q3*k3 - q4*k4 - q5*k5 - q6*k6 - q7*k7;
            o_lo.y = q0*k1 + q1*k0 - q2*k4 + q4*k2 - q3*k5 + q5*k3 - q6*k7 - q7*k6;
            o_lo.z = q0*k2 + q2*k0 + q1*k4 - q4*k1 - q3*k6 + q6*k3 + q5*k7 + q7*k5;
            o_lo.w = q0*k3 + q3*k0 + q1*k5 - q5*k1 + q2*k6 - q6*k2 - q4*k7 - q7*k4;
            o_hi.x = q0*k4 + q4*k0 + q1*k2 - q2*k1 + q3*k7 + q7*k3 - q5*k6 + q6*k5;
            o_hi.y = q0*k5 + q5*k0 + q1*k3 - q3*k1 - q2*k7 - q7*k2 + q4*k6 - q6*k4;
            o_hi.z = q0*k6 + q6*k0 + q2*k3 - q3*k2 + q1*k7 + q7*k1 - q4*k5 + q5*k4;
            o_hi.w = q0*k7 + q7*k0 + q1*k6 + q6*k1 - q2*k5 - q5*k2 + q3*k4 + q4*k3;

            obase[si * S * 2 + t * 2 + 0] = o_lo;
            obase[si * S * 2 + t * 2 + 1] = o_hi;
        }
    }
}

extern "C" void kernel_launch(void* const* d_in, const int* in_sizes, int n_in,
                              void* d_out, int out_size)
{
    const float* x  = (const float*)d_in[0];   // (2, 2048, 8)
    const float* Wq = (const float*)d_in[1];   // (2048, 2048, 4)
    const float* Wk = (const float*)d_in[2];   // (2048, 2048, 4)
    const float* a  = (const float*)d_in[3];   // (3000, 4)
    float* out = (float*)d_out;                // (2, 2048, 2048, 8)

    qk_kernel<<<S, 256>>>(x, Wq, Wk, a);
    gp_kernel<<<dim3(S / STILE, B), 256>>>(out);
}

// round 3
// speedup vs baseline: 1.4062x; 1.4062x over previous
#include <cuda_runtime.h>
#include <math.h>

#define S 2048
#define B 2
#define STILE 4

// Scratch for normalized q and k: [which(q=0,k=1)][b][n][blade] = 256 KB
__device__ __align__(256) float g_qk[2][B][S][8];

// 256-bit global store (sm_100+): one instruction writes 32B/lane,
// lanes 0-3 fully cover one 128B line -> halved store wavefronts.
__device__ __forceinline__ void stg256(float* p, const float4& a, const float4& b)
{
    asm volatile("st.global.v8.f32 [%0], {%1,%2,%3,%4,%5,%6,%7,%8};"
                 :: "l"(p),
                    "f"(a.x), "f"(a.y), "f"(a.z), "f"(a.w),
                    "f"(b.x), "f"(b.y), "f"(b.z), "f"(b.w)
                 : "memory");
}

__device__ __forceinline__ void ldg256(const float* p, float4& a, float4& b)
{
    asm volatile("ld.global.nc.v8.f32 {%0,%1,%2,%3,%4,%5,%6,%7}, [%8];"
                 : "=f"(a.x), "=f"(a.y), "=f"(a.z), "=f"(a.w),
                   "=f"(b.x), "=f"(b.y), "=f"(b.z), "=f"(b.w)
                 : "l"(p));
}

// ---------------------------------------------------------------------------
// Kernel 1: q AND k for row n in one block.
// W streamed with __ldcs (evict-first: don't thrash L1); x loads stay
// L1-cacheable so x (128 KB) becomes L1-resident across blocks on an SM.
// ---------------------------------------------------------------------------
__global__ __launch_bounds__(256) void qk_kernel(
    const float* __restrict__ x,    // (B, S, 8)
    const float* __restrict__ Wq,   // (S, S, 4)
    const float* __restrict__ Wk,   // (S, S, 4)
    const float* __restrict__ a)    // (3000, 4)
{
    const int n   = blockIdx.x;
    const int tid = threadIdx.x;

    const float4* WqR = reinterpret_cast<const float4*>(Wq + (size_t)n * S * 4);
    const float4* WkR = reinterpret_cast<const float4*>(Wk + (size_t)n * S * 4);
    const float4* X   = reinterpret_cast<const float4*>(x);

    float aq[16], ak[16];
#pragma unroll
    for (int i = 0; i < 16; i++) { aq[i] = 0.f; ak[i] = 0.f; }

#pragma unroll 4
    for (int m = tid; m < S; m += 256) {
        float4 wq  = __ldcs(&WqR[m]);     // streaming: evict-first
        float4 wk  = __ldcs(&WkR[m]);     // streaming: evict-first
        float4 x0a = __ldg(&X[m * 2 + 0]);
        float4 x0b = __ldg(&X[m * 2 + 1]);
        float4 x1a = __ldg(&X[(S + m) * 2 + 0]);
        float4 x1b = __ldg(&X[(S + m) * 2 + 1]);

        aq[0]  = fmaf(wq.x, x0a.x, aq[0]);
        aq[1]  = fmaf(wq.y, x0a.y, aq[1]);
        aq[2]  = fmaf(wq.y, x0a.z, aq[2]);
        aq[3]  = fmaf(wq.y, x0a.w, aq[3]);
        aq[4]  = fmaf(wq.z, x0b.x, aq[4]);
        aq[5]  = fmaf(wq.z, x0b.y, aq[5]);
        aq[6]  = fmaf(wq.z, x0b.z, aq[6]);
        aq[7]  = fmaf(wq.w, x0b.w, aq[7]);
        aq[8]  = fmaf(wq.x, x1a.x, aq[8]);
        aq[9]  = fmaf(wq.y, x1a.y, aq[9]);
        aq[10] = fmaf(wq.y, x1a.z, aq[10]);
        aq[11] = fmaf(wq.y, x1a.w, aq[11]);
        aq[12] = fmaf(wq.z, x1b.x, aq[12]);
        aq[13] = fmaf(wq.z, x1b.y, aq[13]);
        aq[14] = fmaf(wq.z, x1b.z, aq[14]);
        aq[15] = fmaf(wq.w, x1b.w, aq[15]);

        ak[0]  = fmaf(wk.x, x0a.x, ak[0]);
        ak[1]  = fmaf(wk.y, x0a.y, ak[1]);
        ak[2]  = fmaf(wk.y, x0a.z, ak[2]);
        ak[3]  = fmaf(wk.y, x0a.w, ak[3]);
        ak[4]  = fmaf(wk.z, x0b.x, ak[4]);
        ak[5]  = fmaf(wk.z, x0b.y, ak[5]);
        ak[6]  = fmaf(wk.z, x0b.z, ak[6]);
        ak[7]  = fmaf(wk.w, x0b.w, ak[7]);
        ak[8]  = fmaf(wk.x, x1a.x, ak[8]);
        ak[9]  = fmaf(wk.y, x1a.y, ak[9]);
        ak[10] = fmaf(wk.y, x1a.z, ak[10]);
        ak[11] = fmaf(wk.y, x1a.w, ak[11]);
        ak[12] = fmaf(wk.z, x1b.x, ak[12]);
        ak[13] = fmaf(wk.z, x1b.y, ak[13]);
        ak[14] = fmaf(wk.z, x1b.z, ak[14]);
        ak[15] = fmaf(wk.w, x1b.w, ak[15]);
    }

#pragma unroll
    for (int i = 0; i < 16; i++) {
#pragma unroll
        for (int off = 16; off > 0; off >>= 1) {
            aq[i] += __shfl_down_sync(0xffffffffu, aq[i], off);
            ak[i] += __shfl_down_sync(0xffffffffu, ak[i], off);
        }
    }

    __shared__ float red[8][32];
    __shared__ float vals[32];          // [0..15]=q (b0,b1), [16..31]=k
    __shared__ float denom[2][B][4];
    const int warp = tid >> 5, lane = tid & 31;
    if (lane == 0) {
#pragma unroll
        for (int i = 0; i < 16; i++) {
            red[warp][i]      = aq[i];
            red[warp][16 + i] = ak[i];
        }
    }
    __syncthreads();

    if (tid < 32) {
        float s = 0.f;
#pragma unroll
        for (int w2 = 0; w2 < 8; w2++) s += red[w2][tid];
        vals[tid] = s;
    }
    __syncthreads();

    if (tid < 4) {
        const int which = tid >> 1, b = tid & 1;
        const float* v = &vals[which * 16 + b * 8];
        float nr[4];
        nr[0] = fabsf(v[0]);
        nr[1] = sqrtf(v[1] * v[1] + v[2] * v[2] + v[3] * v[3]);
        nr[2] = sqrtf(v[4] * v[4] + v[5] * v[5] + v[6] * v[6]);
        nr[3] = fabsf(v[7]);
#pragma unroll
        for (int g = 0; g < 4; g++) {
            float sa = 1.f / (1.f + expf(-a[n * 4 + g]));
            denom[which][b][g] = sa * (nr[g] - 1.f) + 1.f + 1e-6f;
        }
    }
    __syncthreads();

    if (tid < 32) {
        const int which = tid >> 4, r = tid & 15;
        const int b = r >> 3, i = r & 7;
        const int g = (i == 0) ? 0 : (i < 4) ? 1 : (i < 7) ? 2 : 3;
        g_qk[which][b][n][i] = vals[tid] / denom[which][b][g];
    }
}

// ---------------------------------------------------------------------------
// Kernel 2: out[b,s,t,:] = q[b,s,:] (geometric product) k[b,t,:]
// 256-bit loads of K and 256-bit stores of the output.
// ---------------------------------------------------------------------------
__global__ __launch_bounds__(256) void gp_kernel(float* __restrict__ out)
{
    const int s0  = blockIdx.x * STILE;
    const int b   = blockIdx.y;
    const int tid = threadIdx.x;

    float q[STILE][8];
#pragma unroll
    for (int si = 0; si < STILE; si++) {
        const float4 qa = *reinterpret_cast<const float4*>(&g_qk[0][b][s0 + si][0]);
        const float4 qb = *reinterpret_cast<const float4*>(&g_qk[0][b][s0 + si][4]);
        q[si][0] = qa.x; q[si][1] = qa.y; q[si][2] = qa.z; q[si][3] = qa.w;
        q[si][4] = qb.x; q[si][5] = qb.y; q[si][6] = qb.z; q[si][7] = qb.w;
    }

    const float* K = &g_qk[1][b][0][0];
    float* obase = out + (((size_t)b * S + s0) * S) * 8;

#pragma unroll
    for (int it = 0; it < 8; it++) {
        const int t = tid + it * 256;
        float4 ka, kb;
        ldg256(K + t * 8, ka, kb);
        const float k0 = ka.x, k1 = ka.y, k2 = ka.z, k3 = ka.w;
        const float k4 = kb.x, k5 = kb.y, k6 = kb.z, k7 = kb.w;

#pragma unroll
        for (int si = 0; si < STILE; si++) {
            const float q0 = q[si][0], q1 = q[si][1], q2 = q[si][2], q3 = q[si][3];
            const float q4 = q[si][4], q5 = q[si][5], q6 = q[si][6], q7 = q[si][7];

            float4 o_lo, o_hi;
            o_lo.x = q0*k0 + q1*k1 + q2*k2 + q3*k3 - q4*k4 - q5*k5 - q6*k6 - q7*k7;
            o_lo.y = q0*k1 + q1*k0 - q2*k4 + q4*k2 - q3*k5 + q5*k3 - q6*k7 - q7*k6;
            o_lo.z = q0*k2 + q2*k0 + q1*k4 - q4*k1 - q3*k6 + q6*k3 + q5*k7 + q7*k5;
            o_lo.w = q0*k3 + q3*k0 + q1*k5 - q5*k1 + q2*k6 - q6*k2 - q4*k7 - q7*k4;
            o_hi.x = q0*k4 + q4*k0 + q1*k2 - q2*k1 + q3*k7 + q7*k3 - q5*k6 + q6*k5;
            o_hi.y = q0*k5 + q5*k0 + q1*k3 - q3*k1 - q2*k7 - q7*k2 + q4*k6 - q6*k4;
            o_hi.z = q0*k6 + q6*k0 + q2*k3 - q3*k2 + q1*k7 + q7*k1 - q4*k5 + q5*k4;
            o_hi.w = q0*k7 + q7*k0 + q1*k6 + q6*k1 - q2*k5 - q5*k2 + q3*k4 + q4*k3;

            stg256(obase + (size_t)si * S * 8 + t * 8, o_lo, o_hi);
        }
    }
}

extern "C" void kernel_launch(void* const* d_in, const int* in_sizes, int n_in,
                              void* d_out, int out_size)
{
    const float* x  = (const float*)d_in[0];   // (2, 2048, 8)
    const float* Wq = (const float*)d_in[1];   // (2048, 2048, 4)
    const float* Wk = (const float*)d_in[2];   // (2048, 2048, 4)
    const float* a  = (const float*)d_in[3];   // (3000, 4)
    float* out = (float*)d_out;                // (2, 2048, 2048, 8)

    qk_kernel<<<S, 256>>>(x, Wq, Wk, a);
    gp_kernel<<<dim3(S / STILE, B), 256>>>(out);
}

// round 4
// speedup vs baseline: 1.4450x; 1.0276x over previous
#include <cuda_runtime.h>
#include <math.h>

#define S 2048
#define B 2
#define STILE 4

// Scratch for normalized q and k: [which(q=0,k=1)][b][n][blade] = 256 KB
__device__ __align__(256) float g_qk[2][B][S][8];

// 256-bit global store, streaming (evict-first): output is never re-read.
__device__ __forceinline__ void stg256_cs(float* p, const float4& a, const float4& b)
{
    asm volatile("st.global.cs.v8.f32 [%0], {%1,%2,%3,%4,%5,%6,%7,%8};"
                 :: "l"(p),
                    "f"(a.x), "f"(a.y), "f"(a.z), "f"(a.w),
                    "f"(b.x), "f"(b.y), "f"(b.z), "f"(b.w)
                 : "memory");
}

__device__ __forceinline__ void ldg256(const float* p, float4& a, float4& b)
{
    asm volatile("ld.global.nc.v8.f32 {%0,%1,%2,%3,%4,%5,%6,%7}, [%8];"
                 : "=f"(a.x), "=f"(a.y), "=f"(a.z), "=f"(a.w),
                   "=f"(b.x), "=f"(b.y), "=f"(b.z), "=f"(b.w)
                 : "l"(p));
}

// ---------------------------------------------------------------------------
// Kernel 1: q AND k for row n in one block.
// W streamed with __ldcs (evict-first; keeps L1 for x); x loaded with dense
// 256-bit loads (2 instr/m). Full unroll for MLP on the DRAM W stream.
// ---------------------------------------------------------------------------
__global__ __launch_bounds__(256) void qk_kernel(
    const float* __restrict__ x,    // (B, S, 8)
    const float* __restrict__ Wq,   // (S, S, 4)
    const float* __restrict__ Wk,   // (S, S, 4)
    const float* __restrict__ a)    // (3000, 4)
{
    const int n   = blockIdx.x;
    const int tid = threadIdx.x;

    const float4* WqR = reinterpret_cast<const float4*>(Wq + (size_t)n * S * 4);
    const float4* WkR = reinterpret_cast<const float4*>(Wk + (size_t)n * S * 4);

    float aq[16], ak[16];
#pragma unroll
    for (int i = 0; i < 16; i++) { aq[i] = 0.f; ak[i] = 0.f; }

#pragma unroll
    for (int it = 0; it < S / 256; it++) {
        const int m = tid + it * 256;
        float4 wq  = __ldcs(&WqR[m]);     // streaming: evict-first
        float4 wk  = __ldcs(&WkR[m]);     // streaming: evict-first
        float4 x0a, x0b, x1a, x1b;
        ldg256(x + (size_t)m * 8, x0a, x0b);        // b=0, dense 32B
        ldg256(x + (size_t)(S + m) * 8, x1a, x1b);  // b=1, dense 32B

        aq[0]  = fmaf(wq.x, x0a.x, aq[0]);
        aq[1]  = fmaf(wq.y, x0a.y, aq[1]);
        aq[2]  = fmaf(wq.y, x0a.z, aq[2]);
        aq[3]  = fmaf(wq.y, x0a.w, aq[3]);
        aq[4]  = fmaf(wq.z, x0b.x, aq[4]);
        aq[5]  = fmaf(wq.z, x0b.y, aq[5]);
        aq[6]  = fmaf(wq.z, x0b.z, aq[6]);
        aq[7]  = fmaf(wq.w, x0b.w, aq[7]);
        aq[8]  = fmaf(wq.x, x1a.x, aq[8]);
        aq[9]  = fmaf(wq.y, x1a.y, aq[9]);
        aq[10] = fmaf(wq.y, x1a.z, aq[10]);
        aq[11] = fmaf(wq.y, x1a.w, aq[11]);
        aq[12] = fmaf(wq.z, x1b.x, aq[12]);
        aq[13] = fmaf(wq.z, x1b.y, aq[13]);
        aq[14] = fmaf(wq.z, x1b.z, aq[14]);
        aq[15] = fmaf(wq.w, x1b.w, aq[15]);

        ak[0]  = fmaf(wk.x, x0a.x, ak[0]);
        ak[1]  = fmaf(wk.y, x0a.y, ak[1]);
        ak[2]  = fmaf(wk.y, x0a.z, ak[2]);
        ak[3]  = fmaf(wk.y, x0a.w, ak[3]);
        ak[4]  = fmaf(wk.z, x0b.x, ak[4]);
        ak[5]  = fmaf(wk.z, x0b.y, ak[5]);
        ak[6]  = fmaf(wk.z, x0b.z, ak[6]);
        ak[7]  = fmaf(wk.w, x0b.w, ak[7]);
        ak[8]  = fmaf(wk.x, x1a.x, ak[8]);
        ak[9]  = fmaf(wk.y, x1a.y, ak[9]);
        ak[10] = fmaf(wk.y, x1a.z, ak[10]);
        ak[11] = fmaf(wk.y, x1a.w, ak[11]);
        ak[12] = fmaf(wk.z, x1b.x, ak[12]);
        ak[13] = fmaf(wk.z, x1b.y, ak[13]);
        ak[14] = fmaf(wk.z, x1b.z, ak[14]);
        ak[15] = fmaf(wk.w, x1b.w, ak[15]);
    }

#pragma unroll
    for (int i = 0; i < 16; i++) {
#pragma unroll
        for (int off = 16; off > 0; off >>= 1) {
            aq[i] += __shfl_down_sync(0xffffffffu, aq[i], off);
            ak[i] += __shfl_down_sync(0xffffffffu, ak[i], off);
        }
    }

    __shared__ float red[8][32];
    __shared__ float vals[32];          // [0..15]=q (b0,b1), [16..31]=k
    __shared__ float denom[2][B][4];
    const int warp = tid >> 5, lane = tid & 31;
    if (lane == 0) {
#pragma unroll
        for (int i = 0; i < 16; i++) {
            red[warp][i]      = aq[i];
            red[warp][16 + i] = ak[i];
        }
    }
    __syncthreads();

    if (tid < 32) {
        float s = 0.f;
#pragma unroll
        for (int w2 = 0; w2 < 8; w2++) s += red[w2][tid];
        vals[tid] = s;
    }
    __syncthreads();

    if (tid < 4) {
        const int which = tid >> 1, b = tid & 1;
        const float* v = &vals[which * 16 + b * 8];
        float nr[4];
        nr[0] = fabsf(v[0]);
        nr[1] = sqrtf(v[1] * v[1] + v[2] * v[2] + v[3] * v[3]);
        nr[2] = sqrtf(v[4] * v[4] + v[5] * v[5] + v[6] * v[6]);
        nr[3] = fabsf(v[7]);
#pragma unroll
        for (int g = 0; g < 4; g++) {
            float sa = 1.f / (1.f + expf(-a[n * 4 + g]));
            denom[which][b][g] = sa * (nr[g] - 1.f) + 1.f + 1e-6f;
        }
    }
    __syncthreads();

    if (tid < 32) {
        const int which = tid >> 4, r = tid & 15;
        const int b = r >> 3, i = r & 7;
        const int g = (i == 0) ? 0 : (i < 4) ? 1 : (i < 7) ? 2 : 3;
        g_qk[which][b][n][i] = vals[tid] / denom[which][b][g];
    }
}

// ---------------------------------------------------------------------------
// Kernel 2: out[b,s,t,:] = q[b,s,:] (geometric product) k[b,t,:]
// 256-bit K loads, 256-bit streaming stores.
// ---------------------------------------------------------------------------
__global__ __launch_bounds__(256) void gp_kernel(float* __restrict__ out)
{
    const int s0  = blockIdx.x * STILE;
    const int b   = blockIdx.y;
    const int tid = threadIdx.x;

    float q[STILE][8];
#pragma unroll
    for (int si = 0; si < STILE; si++) {
        const float4 qa = *reinterpret_cast<const float4*>(&g_qk[0][b][s0 + si][0]);
        const float4 qb = *reinterpret_cast<const float4*>(&g_qk[0][b][s0 + si][4]);
        q[si][0] = qa.x; q[si][1] = qa.y; q[si][2] = qa.z; q[si][3] = qa.w;
        q[si][4] = qb.x; q[si][5] = qb.y; q[si][6] = qb.z; q[si][7] = qb.w;
    }

    const float* K = &g_qk[1][b][0][0];
    float* obase = out + (((size_t)b * S + s0) * S) * 8;

#pragma unroll
    for (int it = 0; it < 8; it++) {
        const int t = tid + it * 256;
        float4 ka, kb;
        ldg256(K + (size_t)t * 8, ka, kb);
        const float k0 = ka.x, k1 = ka.y, k2 = ka.z, k3 = ka.w;
        const float k4 = kb.x, k5 = kb.y, k6 = kb.z, k7 = kb.w;

#pragma unroll
        for (int si = 0; si < STILE; si++) {
            const float q0 = q[si][0], q1 = q[si][1], q2 = q[si][2], q3 = q[si][3];
            const float q4 = q[si][4], q5 = q[si][5], q6 = q[si][6], q7 = q[si][7];

            float4 o_lo, o_hi;
            o_lo.x = q0*k0 + q1*k1 + q2*k2 + q3*k3 - q4*k4 - q5*k5 - q6*k6 - q7*k7;
            o_lo.y = q0*k1 + q1*k0 - q2*k4 + q4*k2 - q3*k5 + q5*k3 - q6*k7 - q7*k6;
            o_lo.z = q0*k2 + q2*k0 + q1*k4 - q4*k1 - q3*k6 + q6*k3 + q5*k7 + q7*k5;
            o_lo.w = q0*k3 + q3*k0 + q1*k5 - q5*k1 + q2*k6 - q6*k2 - q4*k7 - q7*k4;
            o_hi.x = q0*k4 + q4*k0 + q1*k2 - q2*k1 + q3*k7 + q7*k3 - q5*k6 + q6*k5;
            o_hi.y = q0*k5 + q5*k0 + q1*k3 - q3*k1 - q2*k7 - q7*k2 + q4*k6 - q6*k4;
            o_hi.z = q0*k6 + q6*k0 + q2*k3 - q3*k2 + q1*k7 + q7*k1 - q4*k5 + q5*k4;
            o_hi.w = q0*k7 + q7*k0 + q1*k6 + q6*k1 - q2*k5 - q5*k2 + q3*k4 + q4*k3;

            stg256_cs(obase + (size_t)si * S * 8 + t * 8, o_lo, o_hi);
        }
    }
}

extern "C" void kernel_launch(void* const* d_in, const int* in_sizes, int n_in,
                              void* d_out, int out_size)
{
    const float* x  = (const float*)d_in[0];   // (2, 2048, 8)
    const float* Wq = (const float*)d_in[1];   // (2048, 2048, 4)
    const float* Wk = (const float*)d_in[2];   // (2048, 2048, 4)
    const float* a  = (const float*)d_in[3];   // (3000, 4)
    float* out = (float*)d_out;                // (2, 2048, 2048, 8)

    qk_kernel<<<S, 256>>>(x, Wq, Wk, a);
    gp_kernel<<<dim3(S / STILE, B), 256>>>(out);
}

// round 6
// speedup vs baseline: 1.4849x; 1.0276x over previous
#include <cuda_runtime.h>
#include <math.h>

#define S 2048
#define B 2
#define STILE 4
#define QK_THREADS 512
#define QK_BLOCKS 148

// Scratch for normalized q and k: [which(q=0,k=1)][b][n][blade] = 256 KB
__device__ __align__(256) float g_qk[2][B][S][8];

// 256-bit global store, streaming (evict-first): output is never re-read.
__device__ __forceinline__ void stg256_cs(float* p, const float4& a, const float4& b)
{
    asm volatile("st.global.cs.v8.f32 [%0], {%1,%2,%3,%4,%5,%6,%7,%8};"
                 :: "l"(p),
                    "f"(a.x), "f"(a.y), "f"(a.z), "f"(a.w),
                    "f"(b.x), "f"(b.y), "f"(b.z), "f"(b.w)
                 : "memory");
}

__device__ __forceinline__ void ldg256(const float* p, float4& a, float4& b)
{
    asm volatile("ld.global.nc.v8.f32 {%0,%1,%2,%3,%4,%5,%6,%7}, [%8];"
                 : "=f"(a.x), "=f"(a.y), "=f"(a.z), "=f"(a.w),
                   "=f"(b.x), "=f"(b.y), "=f"(b.z), "=f"(b.w)
                 : "l"(p));
}

// ---------------------------------------------------------------------------
// Kernel 1 (persistent): q/k = normalize(mv_linear(x, W), a)
// 148 blocks x 512 threads. Each thread owns m in {tid, tid+512, tid+1024,
// tid+1536}; its x slice (64 floats) lives in registers for the whole kernel.
// Rows n are grid-strided; per n only W is streamed from DRAM (MLP=8).
// Warp reduction: 32-value butterfly (31 shuffles total; lane L ends with
// the full warp sum of accumulator L).
// ---------------------------------------------------------------------------
__global__ __launch_bounds__(QK_THREADS) void qk_kernel(
    const float* __restrict__ x,    // (B, S, 8)
    const float* __restrict__ Wq,   // (S, S, 4)
    const float* __restrict__ Wk,   // (S, S, 4)
    const float* __restrict__ a)    // (3000, 4)
{
    const int tid  = threadIdx.x;
    const int warp = tid >> 5, lane = tid & 31;

    // x slice into registers: xr[j] = {b0 lo, b0 hi, b1 lo, b1 hi} for m_j
    float4 xr[4][4];
#pragma unroll
    for (int j = 0; j < 4; j++) {
        const int m = tid + QK_THREADS * j;
        ldg256(x + (size_t)m * 8,       xr[j][0], xr[j][1]);
        ldg256(x + (size_t)(S + m) * 8, xr[j][2], xr[j][3]);
    }

    __shared__ float red[QK_THREADS / 32][32];
    __shared__ float vals[32];          // [0..15]=q (b0,b1), [16..31]=k
    __shared__ float denom[2][B][4];

    for (int n = blockIdx.x; n < S; n += gridDim.x) {
        const float4* WqR = reinterpret_cast<const float4*>(Wq + (size_t)n * S * 4);
        const float4* WkR = reinterpret_cast<const float4*>(Wk + (size_t)n * S * 4);

        // Issue all 8 W loads up front (independent -> MLP=8)
        float4 wq[4], wk[4];
#pragma unroll
        for (int j = 0; j < 4; j++) {
            wq[j] = __ldcs(&WqR[tid + QK_THREADS * j]);
            wk[j] = __ldcs(&WkR[tid + QK_THREADS * j]);
        }

        // v[0..15] = q accumulators, v[16..31] = k accumulators
        float v[32];
#pragma unroll
        for (int i = 0; i < 32; i++) v[i] = 0.f;

#pragma unroll
        for (int j = 0; j < 4; j++) {
            const float4 x0a = xr[j][0], x0b = xr[j][1];
            const float4 x1a = xr[j][2], x1b = xr[j][3];
            const float4 q4 = wq[j], k4 = wk[j];

            v[0]  = fmaf(q4.x, x0a.x, v[0]);
            v[1]  = fmaf(q4.y, x0a.y, v[1]);
            v[2]  = fmaf(q4.y, x0a.z, v[2]);
            v[3]  = fmaf(q4.y, x0a.w, v[3]);
            v[4]  = fmaf(q4.z, x0b.x, v[4]);
            v[5]  = fmaf(q4.z, x0b.y, v[5]);
            v[6]  = fmaf(q4.z, x0b.z, v[6]);
            v[7]  = fmaf(q4.w, x0b.w, v[7]);
            v[8]  = fmaf(q4.x, x1a.x, v[8]);
            v[9]  = fmaf(q4.y, x1a.y, v[9]);
            v[10] = fmaf(q4.y, x1a.z, v[10]);
            v[11] = fmaf(q4.y, x1a.w, v[11]);
            v[12] = fmaf(q4.z, x1b.x, v[12]);
            v[13] = fmaf(q4.z, x1b.y, v[13]);
            v[14] = fmaf(q4.z, x1b.z, v[14]);
            v[15] = fmaf(q4.w, x1b.w, v[15]);

            v[16] = fmaf(k4.x, x0a.x, v[16]);
            v[17] = fmaf(k4.y, x0a.y, v[17]);
            v[18] = fmaf(k4.y, x0a.z, v[18]);
            v[19] = fmaf(k4.y, x0a.w, v[19]);
            v[20] = fmaf(k4.z, x0b.x, v[20]);
            v[21] = fmaf(k4.z, x0b.y, v[21]);
            v[22] = fmaf(k4.z, x0b.z, v[22]);
            v[23] = fmaf(k4.w, x0b.w, v[23]);
            v[24] = fmaf(k4.x, x1a.x, v[24]);
            v[25] = fmaf(k4.y, x1a.y, v[25]);
            v[26] = fmaf(k4.y, x1a.z, v[26]);
            v[27] = fmaf(k4.y, x1a.w, v[27]);
            v[28] = fmaf(k4.z, x1b.x, v[28]);
            v[29] = fmaf(k4.z, x1b.y, v[29]);
            v[30] = fmaf(k4.z, x1b.z, v[30]);
            v[31] = fmaf(k4.w, x1b.w, v[31]);
        }

        // Multi-value butterfly: after stages d=16..1, lane L holds the full
        // warp sum of accumulator index L in v[0].
#pragma unroll
        for (int d = 16; d >= 1; d >>= 1) {
#pragma unroll
            for (int i = 0; i < d; i++) {
                const bool hi = (lane & d) != 0;
                const float keep = hi ? v[i + d] : v[i];
                const float send = hi ? v[i] : v[i + d];
                v[i] = keep + __shfl_xor_sync(0xffffffffu, send, d);
            }
        }
        red[warp][lane] = v[0];
        __syncthreads();

        // Final stage entirely inside warp 0
        if (tid < 32) {
            float s = 0.f;
#pragma unroll
            for (int w2 = 0; w2 < QK_THREADS / 32; w2++) s += red[w2][tid];
            vals[tid] = s;
            __syncwarp();

            if (tid < 4) {
                const int which = tid >> 1, b = tid & 1;
                const float* vv = &vals[which * 16 + b * 8];
                float nr[4];
                nr[0] = fabsf(vv[0]);
                nr[1] = sqrtf(vv[1] * vv[1] + vv[2] * vv[2] + vv[3] * vv[3]);
                nr[2] = sqrtf(vv[4] * vv[4] + vv[5] * vv[5] + vv[6] * vv[6]);
                nr[3] = fabsf(vv[7]);
#pragma unroll
                for (int g = 0; g < 4; g++) {
                    float sa = 1.f / (1.f + expf(-a[n * 4 + g]));
                    denom[which][b][g] = sa * (nr[g] - 1.f) + 1.f + 1e-6f;
                }
            }
            __syncwarp();

            const int which = tid >> 4, r = tid & 15;
            const int b = r >> 3, i = r & 7;
            const int g = (i == 0) ? 0 : (i < 4) ? 1 : (i < 7) ? 2 : 3;
            g_qk[which][b][n][i] = vals[tid] / denom[which][b][g];
        }
        __syncthreads();   // protect red/vals reuse next iteration
    }
}

// ---------------------------------------------------------------------------
// Kernel 2: out[b,s,t,:] = q[b,s,:] (geometric product) k[b,t,:]
// 256-bit K loads, 256-bit streaming stores.
// ---------------------------------------------------------------------------
__global__ __launch_bounds__(256) void gp_kernel(float* __restrict__ out)
{
    const int s0  = blockIdx.x * STILE;
    const int b   = blockIdx.y;
    const int tid = threadIdx.x;

    float q[STILE][8];
#pragma unroll
    for (int si = 0; si < STILE; si++) {
        const float4 qa = *reinterpret_cast<const float4*>(&g_qk[0][b][s0 + si][0]);
        const float4 qb = *reinterpret_cast<const float4*>(&g_qk[0][b][s0 + si][4]);
        q[si][0] = qa.x; q[si][1] = qa.y; q[si][2] = qa.z; q[si][3] = qa.w;
        q[si][4] = qb.x; q[si][5] = qb.y; q[si][6] = qb.z; q[si][7] = qb.w;
    }

    const float* K = &g_qk[1][b][0][0];
    float* obase = out + (((size_t)b * S + s0) * S) * 8;

#pragma unroll
    for (int it = 0; it < 8; it++) {
        const int t = tid + it * 256;
        float4 ka, kb;
        ldg256(K + (size_t)t * 8, ka, kb);
        const float k0 = ka.x, k1 = ka.y, k2 = ka.z, k3 = ka.w;
        const float k4 = kb.x, k5 = kb.y, k6 = kb.z, k7 = kb.w;

#pragma unroll
        for (int si = 0; si < STILE; si++) {
            const float q0 = q[si][0], q1 = q[si][1], q2 = q[si][2], q3 = q[si][3];
            const float q4 = q[si][4], q5 = q[si][5], q6 = q[si][6], q7 = q[si][7];

            float4 o_lo, o_hi;
            o_lo.x = q0*k0 + q1*k1 + q2*k2 + q3*k3 - q4*k4 - q5*k5 - q6*k6 - q7*k7;
            o_lo.y = q0*k1 + q1*k0 - q2*k4 + q4*k2 - q3*k5 + q5*k3 - q6*k7 - q7*k6;
            o_lo.z = q0*k2 + q2*k0 + q1*k4 - q4*k1 - q3*k6 + q6*k3 + q5*k7 + q7*k5;
            o_lo.w = q0*k3 + q3*k0 + q1*k5 - q5*k1 + q2*k6 - q6*k2 - q4*k7 - q7*k4;
            o_hi.x = q0*k4 + q4*k0 + q1*k2 - q2*k1 + q3*k7 + q7*k3 - q5*k6 + q6*k5;
            o_hi.y = q0*k5 + q5*k0 + q1*k3 - q3*k1 - q2*k7 - q7*k2 + q4*k6 - q6*k4;
            o_hi.z = q0*k6 + q6*k0 + q2*k3 - q3*k2 + q1*k7 + q7*k1 - q4*k5 + q5*k4;
            o_hi.w = q0*k7 + q7*k0 + q1*k6 + q6*k1 - q2*k5 - q5*k2 + q3*k4 + q4*k3;

            stg256_cs(obase + (size_t)si * S * 8 + t * 8, o_lo, o_hi);
        }
    }
}

extern "C" void kernel_launch(void* const* d_in, const int* in_sizes, int n_in,
                              void* d_out, int out_size)
{
    const float* x  = (const float*)d_in[0];   // (2, 2048, 8)
    const float* Wq = (const float*)d_in[1];   // (2048, 2048, 4)
    const float* Wk = (const float*)d_in[2];   // (2048, 2048, 4)
    const float* a  = (const float*)d_in[3];   // (3000, 4)
    float* out = (float*)d_out;                // (2, 2048, 2048, 8)

    qk_kernel<<<QK_BLOCKS, QK_THREADS>>>(x, Wq, Wk, a);
    gp_kernel<<<dim3(S / STILE, B), 256>>>(out);
}